// round 1
// baseline (speedup 1.0000x reference)
#include <cuda_runtime.h>

// out[b, 0, h, w] = 0.5f * (x[b,0,h,w] + x[b,1,h,w] + x[b,2,h,w])
// Exact algebraic collapse of the diagonal Haar decompose + reconstruct:
//   recon(0::2,1::2) = 0.5*(up_low+up_det) = 0.5*sum_c x01
//   recon(1::2,0::2) = 0.5*(up_low-up_det) = 0.5*sum_c x10
//   recon(0::2,0::2) = 0.5*(dn_low+dn_det) = 0.5*sum_c x00
//   recon(1::2,1::2) = 0.5*(dn_low-dn_det) = 0.5*sum_c x11
// i.e. every output pixel = 0.5 * channel-sum at the same spatial location.

static constexpr int B = 16;
static constexpr int C = 3;
static constexpr int HW = 1024 * 1024;           // H*W per channel plane
static constexpr long long OUT_ELEMS = (long long)B * HW;   // 16,777,216
static constexpr int VEC = 4;                    // float4
static constexpr long long OUT_VECS = OUT_ELEMS / VEC;      // 4,194,304

__global__ void haar_chansum_kernel(const float* __restrict__ x,
                                    float* __restrict__ out) {
    long long v = (long long)blockIdx.x * blockDim.x + threadIdx.x;
    if (v >= OUT_VECS) return;

    long long e = v * VEC;                 // element index in output
    long long b = e / HW;                  // batch
    long long p = e - b * HW;              // pixel within plane
    const float* base = x + (b * C) * (long long)HW + p;

    float4 a0 = *reinterpret_cast<const float4*>(base);
    float4 a1 = *reinterpret_cast<const float4*>(base + HW);
    float4 a2 = *reinterpret_cast<const float4*>(base + 2LL * HW);

    float4 r;
    r.x = 0.5f * (a0.x + a1.x + a2.x);
    r.y = 0.5f * (a0.y + a1.y + a2.y);
    r.z = 0.5f * (a0.z + a1.z + a2.z);
    r.w = 0.5f * (a0.w + a1.w + a2.w);

    *reinterpret_cast<float4*>(out + e) = r;
}

extern "C" void kernel_launch(void* const* d_in, const int* in_sizes, int n_in,
                              void* d_out, int out_size) {
    const float* x = (const float*)d_in[0];
    float* out = (float*)d_out;
    const int threads = 256;
    const int blocks = (int)((OUT_VECS + threads - 1) / threads);
    haar_chansum_kernel<<<blocks, threads>>>(x, out);
}

// round 2
// speedup vs baseline: 1.0069x; 1.0069x over previous
#include <cuda_runtime.h>

// out[b, 0, h, w] = 0.5f * (x[b,0,h,w] + x[b,1,h,w] + x[b,2,h,w])
// Exact algebraic collapse of the diagonal Haar decompose + reconstruct
// (see R0 derivation: every output pixel = 0.5 * channel-sum at same (h,w)).
//
// R2: 2x float4 per thread (6 independent LDG.128 -> MLP=6), streaming
// cache hints (__ldcs/__stcs) since the 268MB working set is touched once
// and exceeds the 126MB L2.

static constexpr int B = 16;
static constexpr int C = 3;
static constexpr long long HW = 1024LL * 1024LL;          // elems per plane (2^20)
static constexpr long long OUT_ELEMS = (long long)B * HW; // 16,777,216
static constexpr int EPT = 8;                             // elements per thread (2x float4)
static constexpr long long N_THREADS = OUT_ELEMS / EPT;   // 2,097,152

__global__ void haar_chansum_kernel(const float* __restrict__ x,
                                    float* __restrict__ out) {
    long long t = (long long)blockIdx.x * blockDim.x + threadIdx.x;
    if (t >= N_THREADS) return;

    long long e = t * EPT;                 // first output element (8-aligned, within one plane)
    long long b = e >> 20;                 // batch index (HW = 2^20)
    long long p = e & (HW - 1);            // pixel within plane
    const float* base = x + (b * C) * HW + p;

    const float4* c0 = reinterpret_cast<const float4*>(base);
    const float4* c1 = reinterpret_cast<const float4*>(base + HW);
    const float4* c2 = reinterpret_cast<const float4*>(base + 2LL * HW);

    // 6 independent 16B loads issued back-to-back (MLP=6)
    float4 a0 = __ldcs(c0 + 0);
    float4 b0 = __ldcs(c0 + 1);
    float4 a1 = __ldcs(c1 + 0);
    float4 b1 = __ldcs(c1 + 1);
    float4 a2 = __ldcs(c2 + 0);
    float4 b2 = __ldcs(c2 + 1);

    float4 r0, r1;
    r0.x = 0.5f * (a0.x + a1.x + a2.x);
    r0.y = 0.5f * (a0.y + a1.y + a2.y);
    r0.z = 0.5f * (a0.z + a1.z + a2.z);
    r0.w = 0.5f * (a0.w + a1.w + a2.w);
    r1.x = 0.5f * (b0.x + b1.x + b2.x);
    r1.y = 0.5f * (b0.y + b1.y + b2.y);
    r1.z = 0.5f * (b0.z + b1.z + b2.z);
    r1.w = 0.5f * (b0.w + b1.w + b2.w);

    float4* o = reinterpret_cast<float4*>(out + e);
    __stcs(o + 0, r0);
    __stcs(o + 1, r1);
}

extern "C" void kernel_launch(void* const* d_in, const int* in_sizes, int n_in,
                              void* d_out, int out_size) {
    const float* x = (const float*)d_in[0];
    float* out = (float*)d_out;
    const int threads = 256;
    const int blocks = (int)((N_THREADS + threads - 1) / threads);
    haar_chansum_kernel<<<blocks, threads>>>(x, out);
}